// round 6
// baseline (speedup 1.0000x reference)
#include <cuda_runtime.h>
#include <cuda_bf16.h>
#include <cstdint>

#define BATCH 4
#define SEQ 2048
#define DM 1024
#define NH 16
#define DEPTH 64
#define MROWS (BATCH * SEQ)  // 8192

typedef __nv_bfloat16 bf16;

// ---------------- scratch (allocation-free rule: __device__ globals) --------
__device__ bf16 g_ihi[3][MROWS * DM];
__device__ bf16 g_ilo[3][MROWS * DM];
__device__ bf16 g_whi[4][DM * DM];
__device__ bf16 g_wlo[4][DM * DM];
__device__ bf16 g_qhi[MROWS * DM], g_qlo[MROWS * DM];
__device__ bf16 g_khi[MROWS * DM], g_klo[MROWS * DM];
__device__ bf16 g_vthi[MROWS * DM], g_vtlo[MROWS * DM];
__device__ bf16 g_ohi[MROWS * DM], g_olo[MROWS * DM];

// ---------------------------- PTX helpers ----------------------------------
__device__ __forceinline__ uint32_t smem_u32(const void* p) {
  uint32_t a;
  asm("{ .reg .u64 t; cvta.to.shared.u64 t, %1; cvt.u32.u64 %0, t; }"
      : "=r"(a) : "l"(p));
  return a;
}
__device__ __forceinline__ void cp_async16(uint32_t dst, const void* src) {
  asm volatile("cp.async.cg.shared.global [%0], [%1], 16;" ::"r"(dst),
               "l"(src));
}
#define CP_COMMIT() asm volatile("cp.async.commit_group;" ::: "memory")
#define CP_WAIT(n) asm volatile("cp.async.wait_group %0;" ::"n"(n) : "memory")

#define MMA16816(d, a, b)                                                   \
  asm volatile(                                                             \
      "mma.sync.aligned.m16n8k16.row.col.f32.bf16.bf16.f32 "                \
      "{%0,%1,%2,%3}, {%4,%5,%6,%7}, {%8,%9}, {%0,%1,%2,%3};"               \
      : "+f"((d)[0]), "+f"((d)[1]), "+f"((d)[2]), "+f"((d)[3])              \
      : "r"((a)[0]), "r"((a)[1]), "r"((a)[2]), "r"((a)[3]), "r"((b)[0]),    \
        "r"((b)[1]))

// pack two floats into bf16x2 hi and lo (split-precision) words
__device__ __forceinline__ void split_pack2(float a, float b, uint32_t& hi,
                                            uint32_t& lo) {
  bf16 ha = __float2bfloat16_rn(a), hb = __float2bfloat16_rn(b);
  bf16 la = __float2bfloat16_rn(a - __bfloat162float(ha));
  bf16 lb = __float2bfloat16_rn(b - __bfloat162float(hb));
  __nv_bfloat162 h2 = __halves2bfloat162(ha, hb);
  __nv_bfloat162 l2 = __halves2bfloat162(la, lb);
  hi = *reinterpret_cast<uint32_t*>(&h2);
  lo = *reinterpret_cast<uint32_t*>(&l2);
}

// ---------------------------------------------------------------------------
// batched fp32 -> bf16 hi/lo split (up to 4 tensors per launch, z selects)
// ---------------------------------------------------------------------------
struct SplitArgs {
  const float* src[4];
  bf16* hi[4];
  bf16* lo[4];
};

__global__ __launch_bounds__(256) void split_batch(SplitArgs a, int n4) {
  const int z = blockIdx.y;
  const int i = blockIdx.x * 256 + threadIdx.x;
  if (i >= n4) return;
  float4 v = ((const float4*)a.src[z])[i];
  uint32_t h0, l0, h1, l1;
  split_pack2(v.x, v.y, h0, l0);
  split_pack2(v.z, v.w, h1, l1);
  ((uint32_t*)a.hi[z])[2 * i + 0] = h0;
  ((uint32_t*)a.hi[z])[2 * i + 1] = h1;
  ((uint32_t*)a.lo[z])[2 * i + 0] = l0;
  ((uint32_t*)a.lo[z])[2 * i + 1] = l1;
}

// ---------------------------------------------------------------------------
// Shared bf16x3 GEMM core: 128x128 tile, 3-stage cp.async ring, 8 warps.
// ---------------------------------------------------------------------------
#define BKG 64
#define NITERG (DM / BKG)                 // 16
#define TSTRIDE_B 144                     // bytes per smem row (72 bf16)
#define TILE_BYTES (128 * TSTRIDE_B)      // 18432
#define STAGE_BYTES (4 * TILE_BYTES)      // 73728
#define GEMM_SMEM (3 * STAGE_BYTES)       // 221184

__device__ __forceinline__ void gemm_core(
    const bf16* __restrict__ Ahi, const bf16* __restrict__ Alo,
    const bf16* __restrict__ Whi, const bf16* __restrict__ Wlo, char* sm,
    int tid, int brow, int bcol, float (&acc)[4][4][4]) {
  const bf16* srcs[4] = {Ahi + (size_t)brow * DM, Alo + (size_t)brow * DM,
                         Whi + (size_t)bcol * DM, Wlo + (size_t)bcol * DM};

  auto load_stage = [&](int iter, int s) {
    char* base = sm + s * STAGE_BYTES;
    const int k0 = iter * BKG;
#pragma unroll
    for (int t = 0; t < 4; t++) {
      char* tb = base + t * TILE_BYTES;
      const bf16* gsrc = srcs[t] + k0;
#pragma unroll
      for (int i = tid; i < 1024; i += 256) {
        const int row = i >> 3, c = i & 7;
        cp_async16(smem_u32(tb + row * TSTRIDE_B + c * 16),
                   gsrc + (size_t)row * DM + c * 8);
      }
    }
    CP_COMMIT();
  };

  const int wid = tid >> 5, lane = tid & 31;
  const int g = lane >> 2, tg = lane & 3;
  const int warp_m = (wid & 1) * 64;
  const int warp_n = (wid >> 1) * 32;

#pragma unroll
  for (int mi = 0; mi < 4; mi++)
#pragma unroll
    for (int ni = 0; ni < 4; ni++)
#pragma unroll
      for (int r = 0; r < 4; r++) acc[mi][ni][r] = 0.f;

  load_stage(0, 0);
  load_stage(1, 1);

  for (int it = 0; it < NITERG; it++) {
    if (it + 2 < NITERG) {
      load_stage(it + 2, (it + 2) % 3);
      CP_WAIT(2);
    } else if (it + 1 < NITERG) {
      CP_WAIT(1);
    } else {
      CP_WAIT(0);
    }
    __syncthreads();
    const char* base = sm + (it % 3) * STAGE_BYTES;
    const char* pAhi = base + 0 * TILE_BYTES;
    const char* pAlo = base + 1 * TILE_BYTES;
    const char* pWhi = base + 2 * TILE_BYTES;
    const char* pWlo = base + 3 * TILE_BYTES;

#pragma unroll
    for (int k16 = 0; k16 < 4; k16++) {
      const int kcb = (k16 * 16 + tg * 2) * 2;
      uint32_t ahi[4][4], alo[4][4], bhi[4][2], blo[4][2];
#pragma unroll
      for (int mi = 0; mi < 4; mi++) {
        const int r0 = (warp_m + mi * 16 + g) * TSTRIDE_B + kcb;
        const int r1 = r0 + 8 * TSTRIDE_B;
        ahi[mi][0] = *(const uint32_t*)(pAhi + r0);
        ahi[mi][1] = *(const uint32_t*)(pAhi + r1);
        ahi[mi][2] = *(const uint32_t*)(pAhi + r0 + 16);
        ahi[mi][3] = *(const uint32_t*)(pAhi + r1 + 16);
        alo[mi][0] = *(const uint32_t*)(pAlo + r0);
        alo[mi][1] = *(const uint32_t*)(pAlo + r1);
        alo[mi][2] = *(const uint32_t*)(pAlo + r0 + 16);
        alo[mi][3] = *(const uint32_t*)(pAlo + r1 + 16);
      }
#pragma unroll
      for (int ni = 0; ni < 4; ni++) {
        const int r = (warp_n + ni * 8 + g) * TSTRIDE_B + kcb;
        bhi[ni][0] = *(const uint32_t*)(pWhi + r);
        bhi[ni][1] = *(const uint32_t*)(pWhi + r + 16);
        blo[ni][0] = *(const uint32_t*)(pWlo + r);
        blo[ni][1] = *(const uint32_t*)(pWlo + r + 16);
      }
#pragma unroll
      for (int mi = 0; mi < 4; mi++)
#pragma unroll
        for (int ni = 0; ni < 4; ni++) {
          MMA16816(acc[mi][ni], ahi[mi], bhi[ni]);
          MMA16816(acc[mi][ni], ahi[mi], blo[ni]);
          MMA16816(acc[mi][ni], alo[mi], bhi[ni]);
        }
    }
    __syncthreads();
  }
}

// ---------------------------------------------------------------------------
// Batched projection GEMM: z = 0(Q, scale 1/8), 1(K), 2(V, transposed out)
// outputs bf16 hi/lo. Q/K: head-split (B,H,S,d). V: (B,H,d,S).
// ---------------------------------------------------------------------------
struct ProjArgs {
  const bf16* ahi[3];
  const bf16* alo[3];
  const bf16* whi[3];
  const bf16* wlo[3];
  const float* bias[3];
  bf16* chi[3];
  bf16* clo[3];
};

__global__ __launch_bounds__(256, 1) void proj_gemm(ProjArgs p) {
  extern __shared__ char sm[];
  const int tid = threadIdx.x;
  const int z = blockIdx.z;
  const int brow = blockIdx.y * 128;
  const int bcol = blockIdx.x * 128;

  float acc[4][4][4];
  gemm_core(p.ahi[z], p.alo[z], p.whi[z], p.wlo[z], sm, tid, brow, bcol, acc);

  const int wid = tid >> 5, lane = tid & 31;
  const int g = lane >> 2, tg = lane & 3;
  const int warp_m = (wid & 1) * 64;
  const int warp_n = (wid >> 1) * 32;
  const float* bias = p.bias[z];
  bf16* Chi = p.chi[z];
  bf16* Clo = p.clo[z];
  const float sc = (z == 0) ? 0.125f : 1.0f;

#pragma unroll
  for (int mi = 0; mi < 4; mi++) {
    const int m0 = brow + warp_m + mi * 16 + g;
    const int m1 = m0 + 8;
#pragma unroll
    for (int ni = 0; ni < 4; ni++) {
      const int n = bcol + warp_n + ni * 8 + tg * 2;
      const float bx = bias[n], by = bias[n + 1];
      const float v0 = (acc[mi][ni][0] + bx) * sc, v1 = (acc[mi][ni][1] + by) * sc;
      const float v2 = (acc[mi][ni][2] + bx) * sc, v3 = (acc[mi][ni][3] + by) * sc;
      if (z < 2) {
        uint32_t h, l;
        const int i0 = ((m0 >> 11) * NH + (n >> 6)) * (SEQ * DEPTH) +
                       (m0 & (SEQ - 1)) * DEPTH + (n & (DEPTH - 1));
        split_pack2(v0, v1, h, l);
        *(uint32_t*)(Chi + i0) = h;
        *(uint32_t*)(Clo + i0) = l;
        const int i1 = ((m1 >> 11) * NH + (n >> 6)) * (SEQ * DEPTH) +
                       (m1 & (SEQ - 1)) * DEPTH + (n & (DEPTH - 1));
        split_pack2(v2, v3, h, l);
        *(uint32_t*)(Chi + i1) = h;
        *(uint32_t*)(Clo + i1) = l;
      } else {
        // transposed head-split: idx = ((b*NH+h)*DEPTH + d)*SEQ + s
        const int hh = n >> 6, d0 = n & 63;
        const float vals[4] = {v0, v1, v2, v3};
        const int ms[2] = {m0, m1};
#pragma unroll
        for (int rr = 0; rr < 2; rr++) {
          const int bb = ms[rr] >> 11, s = ms[rr] & (SEQ - 1);
#pragma unroll
          for (int e = 0; e < 2; e++) {
            const float val = vals[rr * 2 + e];
            const size_t idx =
                ((size_t)(bb * NH + hh) * DEPTH + d0 + e) * SEQ + s;
            bf16 hv = __float2bfloat16_rn(val);
            Chi[idx] = hv;
            Clo[idx] = __float2bfloat16_rn(val - __bfloat162float(hv));
          }
        }
      }
    }
  }
}

// ---------------------------------------------------------------------------
// Dense output GEMM: fp32 row-major out
// ---------------------------------------------------------------------------
__global__ __launch_bounds__(256, 1) void dense_gemm(
    const bf16* __restrict__ Ahi, const bf16* __restrict__ Alo,
    const bf16* __restrict__ Whi, const bf16* __restrict__ Wlo,
    const float* __restrict__ bias, float* __restrict__ Cf) {
  extern __shared__ char sm[];
  const int tid = threadIdx.x;
  const int brow = blockIdx.y * 128;
  const int bcol = blockIdx.x * 128;

  float acc[4][4][4];
  gemm_core(Ahi, Alo, Whi, Wlo, sm, tid, brow, bcol, acc);

  const int wid = tid >> 5, lane = tid & 31;
  const int g = lane >> 2, tg = lane & 3;
  const int warp_m = (wid & 1) * 64;
  const int warp_n = (wid >> 1) * 32;

#pragma unroll
  for (int mi = 0; mi < 4; mi++) {
    const int m0 = brow + warp_m + mi * 16 + g;
    const int m1 = m0 + 8;
#pragma unroll
    for (int ni = 0; ni < 4; ni++) {
      const int n = bcol + warp_n + ni * 8 + tg * 2;
      const float bx = bias[n], by = bias[n + 1];
      *(float2*)(Cf + (size_t)m0 * DM + n) =
          make_float2(acc[mi][ni][0] + bx, acc[mi][ni][1] + by);
      *(float2*)(Cf + (size_t)m1 * DM + n) =
          make_float2(acc[mi][ni][2] + bx, acc[mi][ni][3] + by);
    }
  }
}

// ---------------------------------------------------------------------------
// Tensor-core causal flash attention, 128-row Q tiles, 8 warps.
// K-tile 64; smem per stage: Khi,Klo [key][d], Vthi,Vtlo [d][key].
// Q pre-scaled by 1/8 at projection. Mask applies only when kt >= 2*qt.
// ---------------------------------------------------------------------------
#define FSTRIDE 144
#define FTILE_B (64 * FSTRIDE)     // 9216
#define FSTAGE_B (4 * FTILE_B)     // 36864
#define FLASH_SMEM (2 * FSTAGE_B)  // 73728

__global__ __launch_bounds__(256, 1) void flash_mma(
    const bf16* __restrict__ Qhi, const bf16* __restrict__ Qlo,
    const bf16* __restrict__ Khi, const bf16* __restrict__ Klo,
    const bf16* __restrict__ Vthi, const bf16* __restrict__ Vtlo,
    bf16* __restrict__ Ohi, bf16* __restrict__ Olo) {
  extern __shared__ char sm[];
  const int tid = threadIdx.x;
  const int warp = tid >> 5, lane = tid & 31;
  const int g = lane >> 2, tg = lane & 3;
  const int qt = blockIdx.x, bh = blockIdx.y;
  const int NT = 2 * qt + 2;  // K tiles to visit

  const bf16* kb_hi = Khi + (size_t)bh * SEQ * DEPTH;
  const bf16* kb_lo = Klo + (size_t)bh * SEQ * DEPTH;
  const bf16* vb_hi = Vthi + (size_t)bh * DEPTH * SEQ;
  const bf16* vb_lo = Vtlo + (size_t)bh * DEPTH * SEQ;

  auto load_kv = [&](int kt, int st) {
    char* base = sm + st * FSTAGE_B;
    const bf16* khs = kb_hi + kt * 64 * DEPTH;
    const bf16* kls = kb_lo + kt * 64 * DEPTH;
#pragma unroll
    for (int i = tid; i < 512; i += 256) {
      const int r = i >> 3, c = i & 7;
      const uint32_t d0 = smem_u32(base + r * FSTRIDE + c * 16);
      cp_async16(d0, khs + r * DEPTH + c * 8);
      cp_async16(d0 + FTILE_B, kls + r * DEPTH + c * 8);
    }
    const bf16* vhs = vb_hi + kt * 64;
    const bf16* vls = vb_lo + kt * 64;
#pragma unroll
    for (int i = tid; i < 512; i += 256) {
      const int r = i >> 3, c = i & 7;
      const uint32_t d0 = smem_u32(base + 2 * FTILE_B + r * FSTRIDE + c * 16);
      cp_async16(d0, vhs + (size_t)r * SEQ + c * 8);
      cp_async16(d0 + FTILE_B, vls + (size_t)r * SEQ + c * 8);
    }
    CP_COMMIT();
  };

  // Q fragments (held for the whole block); Q already scaled by 1/8
  uint32_t qfh[4][4], qfl[4][4];
  {
    const bf16* qb_hi =
        Qhi + (size_t)(bh * SEQ + qt * 128 + warp * 16) * DEPTH;
    const bf16* qb_lo =
        Qlo + (size_t)(bh * SEQ + qt * 128 + warp * 16) * DEPTH;
#pragma unroll
    for (int kb = 0; kb < 4; kb++) {
      const int c0 = kb * 16 + tg * 2;
      qfh[kb][0] = *(const uint32_t*)(qb_hi + g * DEPTH + c0);
      qfh[kb][1] = *(const uint32_t*)(qb_hi + (g + 8) * DEPTH + c0);
      qfh[kb][2] = *(const uint32_t*)(qb_hi + g * DEPTH + c0 + 8);
      qfh[kb][3] = *(const uint32_t*)(qb_hi + (g + 8) * DEPTH + c0 + 8);
      qfl[kb][0] = *(const uint32_t*)(qb_lo + g * DEPTH + c0);
      qfl[kb][1] = *(const uint32_t*)(qb_lo + (g + 8) * DEPTH + c0);
      qfl[kb][2] = *(const uint32_t*)(qb_lo + g * DEPTH + c0 + 8);
      qfl[kb][3] = *(const uint32_t*)(qb_lo + (g + 8) * DEPTH + c0 + 8);
    }
  }

  float o[8][4];
#pragma unroll
  for (int nb = 0; nb < 8; nb++)
#pragma unroll
    for (int r = 0; r < 4; r++) o[nb][r] = 0.f;
  float m0 = -1e30f, m1 = -1e30f, l0 = 0.f, l1 = 0.f;

  const int row_max = qt * 128 + warp * 16 + 15;  // last row this warp owns

  load_kv(0, 0);

  for (int kt = 0; kt < NT; kt++) {
    if (kt + 1 < NT) {
      load_kv(kt + 1, (kt + 1) & 1);
      CP_WAIT(1);
    } else {
      CP_WAIT(0);
    }
    __syncthreads();
    const char* base = sm + (kt & 1) * FSTAGE_B;

    if (kt * 64 <= row_max) {  // warp-uniform: skip fully-masked tiles
      // S = Q K^T (bf16x3)
      float sacc[8][4];
#pragma unroll
      for (int nb = 0; nb < 8; nb++)
#pragma unroll
        for (int r = 0; r < 4; r++) sacc[nb][r] = 0.f;
#pragma unroll
      for (int nb = 0; nb < 8; nb++) {
        const char* krow = base + (nb * 8 + g) * FSTRIDE;
#pragma unroll
        for (int kb = 0; kb < 4; kb++) {
          const int off = kb * 32 + tg * 4;
          uint32_t Bh[2], Bl[2];
          Bh[0] = *(const uint32_t*)(krow + off);
          Bh[1] = *(const uint32_t*)(krow + off + 16);
          Bl[0] = *(const uint32_t*)(krow + FTILE_B + off);
          Bl[1] = *(const uint32_t*)(krow + FTILE_B + off + 16);
          MMA16816(sacc[nb], qfh[kb], Bh);
          MMA16816(sacc[nb], qfh[kb], Bl);
          MMA16816(sacc[nb], qfl[kb], Bh);
        }
      }

      // causal mask — only the last two tiles can touch the diagonal
      if (kt >= 2 * qt) {
        const int r0g = qt * 128 + warp * 16 + g, r1g = r0g + 8;
        const int cb = kt * 64;
#pragma unroll
        for (int nb = 0; nb < 8; nb++) {
          const int c = cb + nb * 8 + tg * 2;
          if (c > r0g) sacc[nb][0] = -1e9f;
          if (c + 1 > r0g) sacc[nb][1] = -1e9f;
          if (c > r1g) sacc[nb][2] = -1e9f;
          if (c + 1 > r1g) sacc[nb][3] = -1e9f;
        }
      }

      // online softmax (rows g and g+8)
      float mx0 = -1e30f, mx1 = -1e30f;
#pragma unroll
      for (int nb = 0; nb < 8; nb++) {
        mx0 = fmaxf(mx0, fmaxf(sacc[nb][0], sacc[nb][1]));
        mx1 = fmaxf(mx1, fmaxf(sacc[nb][2], sacc[nb][3]));
      }
      mx0 = fmaxf(mx0, __shfl_xor_sync(0xffffffffu, mx0, 1));
      mx0 = fmaxf(mx0, __shfl_xor_sync(0xffffffffu, mx0, 2));
      mx1 = fmaxf(mx1, __shfl_xor_sync(0xffffffffu, mx1, 1));
      mx1 = fmaxf(mx1, __shfl_xor_sync(0xffffffffu, mx1, 2));
      const float mn0 = fmaxf(m0, mx0), mn1 = fmaxf(m1, mx1);
      const float al0 = __expf(m0 - mn0), al1 = __expf(m1 - mn1);
      m0 = mn0;
      m1 = mn1;
      float rs0 = 0.f, rs1 = 0.f;
#pragma unroll
      for (int nb = 0; nb < 8; nb++) {
        sacc[nb][0] = __expf(sacc[nb][0] - mn0);
        sacc[nb][1] = __expf(sacc[nb][1] - mn0);
        sacc[nb][2] = __expf(sacc[nb][2] - mn1);
        sacc[nb][3] = __expf(sacc[nb][3] - mn1);
        rs0 += sacc[nb][0] + sacc[nb][1];
        rs1 += sacc[nb][2] + sacc[nb][3];
      }
      rs0 += __shfl_xor_sync(0xffffffffu, rs0, 1);
      rs0 += __shfl_xor_sync(0xffffffffu, rs0, 2);
      rs1 += __shfl_xor_sync(0xffffffffu, rs1, 1);
      rs1 += __shfl_xor_sync(0xffffffffu, rs1, 2);
      l0 = l0 * al0 + rs0;
      l1 = l1 * al1 + rs1;
#pragma unroll
      for (int nb = 0; nb < 8; nb++) {
        o[nb][0] *= al0;
        o[nb][1] *= al0;
        o[nb][2] *= al1;
        o[nb][3] *= al1;
      }

      // P fragments (hi/lo) straight from S accumulators
      uint32_t pfh[4][4], pfl[4][4];
#pragma unroll
      for (int j = 0; j < 4; j++) {
        split_pack2(sacc[2 * j][0], sacc[2 * j][1], pfh[j][0], pfl[j][0]);
        split_pack2(sacc[2 * j][2], sacc[2 * j][3], pfh[j][1], pfl[j][1]);
        split_pack2(sacc[2 * j + 1][0], sacc[2 * j + 1][1], pfh[j][2],
                    pfl[j][2]);
        split_pack2(sacc[2 * j + 1][2], sacc[2 * j + 1][3], pfh[j][3],
                    pfl[j][3]);
      }

      // O += P V (bf16x3)
#pragma unroll
      for (int nb = 0; nb < 8; nb++) {
        const char* vrow = base + 2 * FTILE_B + (nb * 8 + g) * FSTRIDE;
#pragma unroll
        for (int j = 0; j < 4; j++) {
          const int off = j * 32 + tg * 4;
          uint32_t Vh[2], Vl[2];
          Vh[0] = *(const uint32_t*)(vrow + off);
          Vh[1] = *(const uint32_t*)(vrow + off + 16);
          Vl[0] = *(const uint32_t*)(vrow + FTILE_B + off);
          Vl[1] = *(const uint32_t*)(vrow + FTILE_B + off + 16);
          MMA16816(o[nb], pfh[j], Vh);
          MMA16816(o[nb], pfh[j], Vl);
          MMA16816(o[nb], pfl[j], Vh);
        }
      }
    }
    __syncthreads();
  }

  // epilogue -> row-major (m, DM) bf16 hi/lo for the dense GEMM
  const float inv0 = 1.0f / l0, inv1 = 1.0f / l1;
  const int bb = bh >> 4, hh = bh & 15;
  const int s0 = qt * 128 + warp * 16 + g;
  const size_t row0 = ((size_t)bb * SEQ + s0) * DM + hh * 64;
  const size_t row1 = row0 + (size_t)8 * DM;
#pragma unroll
  for (int nb = 0; nb < 8; nb++) {
    const int col = nb * 8 + tg * 2;
    uint32_t h, l;
    split_pack2(o[nb][0] * inv0, o[nb][1] * inv0, h, l);
    *(uint32_t*)(Ohi + row0 + col) = h;
    *(uint32_t*)(Olo + row0 + col) = l;
    split_pack2(o[nb][2] * inv1, o[nb][3] * inv1, h, l);
    *(uint32_t*)(Ohi + row1 + col) = h;
    *(uint32_t*)(Olo + row1 + col) = l;
  }
}

// ---------------------------------------------------------------------------
extern "C" void kernel_launch(void* const* d_in, const int* in_sizes, int n_in,
                              void* d_out, int out_size) {
  const float* q = (const float*)d_in[0];
  const float* k = (const float*)d_in[1];
  const float* v = (const float*)d_in[2];
  const float* wq_w = (const float*)d_in[3];
  const float* wq_b = (const float*)d_in[4];
  const float* wk_w = (const float*)d_in[5];
  const float* wk_b = (const float*)d_in[6];
  const float* wv_w = (const float*)d_in[7];
  const float* wv_b = (const float*)d_in[8];
  const float* dense_w = (const float*)d_in[9];
  const float* dense_b = (const float*)d_in[10];
  float* out = (float*)d_out;

  bf16 *ihi, *ilo, *whi, *wlo, *qhi, *qlo, *khi, *klo, *vthi, *vtlo, *ohi,
      *olo;
  cudaGetSymbolAddress((void**)&ihi, g_ihi);
  cudaGetSymbolAddress((void**)&ilo, g_ilo);
  cudaGetSymbolAddress((void**)&whi, g_whi);
  cudaGetSymbolAddress((void**)&wlo, g_wlo);
  cudaGetSymbolAddress((void**)&qhi, g_qhi);
  cudaGetSymbolAddress((void**)&qlo, g_qlo);
  cudaGetSymbolAddress((void**)&khi, g_khi);
  cudaGetSymbolAddress((void**)&klo, g_klo);
  cudaGetSymbolAddress((void**)&vthi, g_vthi);
  cudaGetSymbolAddress((void**)&vtlo, g_vtlo);
  cudaGetSymbolAddress((void**)&ohi, g_ohi);
  cudaGetSymbolAddress((void**)&olo, g_olo);

  cudaFuncSetAttribute(proj_gemm, cudaFuncAttributeMaxDynamicSharedMemorySize,
                       GEMM_SMEM);
  cudaFuncSetAttribute(dense_gemm, cudaFuncAttributeMaxDynamicSharedMemorySize,
                       GEMM_SMEM);
  cudaFuncSetAttribute(flash_mma, cudaFuncAttributeMaxDynamicSharedMemorySize,
                       FLASH_SMEM);

  const size_t ISZ = (size_t)MROWS * DM;
  const size_t WSZ = (size_t)DM * DM;
  const int n4_in = MROWS * DM / 4;  // 2M
  const int n4_w = DM * DM / 4;      // 256K

  // input splits (q, k, v) in one launch
  SplitArgs sin;
  sin.src[0] = q; sin.src[1] = k; sin.src[2] = v; sin.src[3] = nullptr;
  sin.hi[0] = ihi + 0 * ISZ; sin.hi[1] = ihi + 1 * ISZ; sin.hi[2] = ihi + 2 * ISZ;
  sin.lo[0] = ilo + 0 * ISZ; sin.lo[1] = ilo + 1 * ISZ; sin.lo[2] = ilo + 2 * ISZ;
  sin.hi[3] = nullptr; sin.lo[3] = nullptr;
  split_batch<<<dim3(n4_in / 256, 3), 256>>>(sin, n4_in);

  // weight splits (wq, wk, wv, dense) in one launch
  SplitArgs sw;
  sw.src[0] = wq_w; sw.src[1] = wk_w; sw.src[2] = wv_w; sw.src[3] = dense_w;
  sw.hi[0] = whi + 0 * WSZ; sw.hi[1] = whi + 1 * WSZ;
  sw.hi[2] = whi + 2 * WSZ; sw.hi[3] = whi + 3 * WSZ;
  sw.lo[0] = wlo + 0 * WSZ; sw.lo[1] = wlo + 1 * WSZ;
  sw.lo[2] = wlo + 2 * WSZ; sw.lo[3] = wlo + 3 * WSZ;
  split_batch<<<dim3(n4_w / 256, 4), 256>>>(sw, n4_w);

  // batched Q/K/V projections (Q pre-scaled by 1/8, V transposed)
  ProjArgs pa;
  pa.ahi[0] = ihi + 0 * ISZ; pa.alo[0] = ilo + 0 * ISZ;
  pa.ahi[1] = ihi + 1 * ISZ; pa.alo[1] = ilo + 1 * ISZ;
  pa.ahi[2] = ihi + 2 * ISZ; pa.alo[2] = ilo + 2 * ISZ;
  pa.whi[0] = whi + 0 * WSZ; pa.wlo[0] = wlo + 0 * WSZ;
  pa.whi[1] = whi + 1 * WSZ; pa.wlo[1] = wlo + 1 * WSZ;
  pa.whi[2] = whi + 2 * WSZ; pa.wlo[2] = wlo + 2 * WSZ;
  pa.bias[0] = wq_b; pa.bias[1] = wk_b; pa.bias[2] = wv_b;
  pa.chi[0] = qhi; pa.clo[0] = qlo;
  pa.chi[1] = khi; pa.clo[1] = klo;
  pa.chi[2] = vthi; pa.clo[2] = vtlo;
  proj_gemm<<<dim3(DM / 128, MROWS / 128, 3), 256, GEMM_SMEM>>>(pa);

  // attention (128-row Q tiles)
  flash_mma<<<dim3(SEQ / 128, BATCH * NH), 256, FLASH_SMEM>>>(
      qhi, qlo, khi, klo, vthi, vtlo, ohi, olo);

  // output projection
  dense_gemm<<<dim3(DM / 128, MROWS / 128), 256, GEMM_SMEM>>>(
      ohi, olo, whi + 3 * WSZ, wlo + 3 * WSZ, dense_b, out);
}